// round 12
// baseline (speedup 1.0000x reference)
#include <cuda_runtime.h>
#include <cuda_bf16.h>
#include <cstdint>
#include <math.h>

#define BATCH 8
#define CC 512
#define NN 4096
#define RR 64
#define EPSV 1e-6f
#define NSTEPS 6
typedef __nv_bfloat16 bf16;
#define F2B(v) __float2bfloat16(v)
#define B2F(v) __bfloat162float(v)

__device__ __forceinline__ uint32_t smem_u32(const void* p) {
    uint32_t a;
    asm("{ .reg .u64 t; cvta.to.shared.u64 t, %1; cvt.u32.u64 %0, t; }" : "=r"(a) : "l"(p));
    return a;
}
__device__ __forceinline__ void cpa16(uint32_t s, const void* g) {
    asm volatile("cp.async.cg.shared.global [%0], [%1], 16;" :: "r"(s), "l"(g));
}
__device__ __forceinline__ void cpa16ca(uint32_t s, const void* g) {
    asm volatile("cp.async.ca.shared.global [%0], [%1], 16;" :: "r"(s), "l"(g));
}
#define CP_COMMIT() asm volatile("cp.async.commit_group;" ::: "memory")
#define CP_WAIT1()  asm volatile("cp.async.wait_group 1;" ::: "memory")
__device__ __forceinline__ void ldsm4(uint32_t* d, uint32_t addr) {
    asm volatile("ldmatrix.sync.aligned.m8n8.x4.shared.b16 {%0,%1,%2,%3}, [%4];"
        : "=r"(d[0]), "=r"(d[1]), "=r"(d[2]), "=r"(d[3]) : "r"(addr));
}
__device__ __forceinline__ void mma16816(float* c, const uint32_t* a, const uint32_t* b) {
    asm volatile("mma.sync.aligned.m16n8k16.row.col.f32.bf16.bf16.f32 "
        "{%0,%1,%2,%3}, {%4,%5,%6,%7}, {%8,%9}, {%0,%1,%2,%3};"
        : "+f"(c[0]), "+f"(c[1]), "+f"(c[2]), "+f"(c[3])
        : "r"(a[0]), "r"(a[1]), "r"(a[2]), "r"(a[3]), "r"(b[0]), "r"(b[1]));
}
__device__ __forceinline__ void store_pair2(bf16* hi, bf16* lo, size_t idx, float v0, float v1) {
    bf16 h0 = F2B(v0), h1 = F2B(v1);
    *(__nv_bfloat162*)(hi + idx) = __halves2bfloat162(h0, h1);
    *(__nv_bfloat162*)(lo + idx) =
        __halves2bfloat162(F2B(v0 - B2F(h0)), F2B(v1 - B2F(h1)));
}

// -------- scratch --------
__device__ float g_bases[BATCH * CC * RR];
__device__ float g_coef[BATCH * NN * RR];
__device__ float g_btbp[BATCH * 8 * RR * RR];
__device__ float g_ctcp[BATCH * 16 * RR * RR];
__device__ float g_xcp[BATCH * 8 * CC * RR];
__device__ bf16 g_WLh[CC * CC], g_WLl[CC * CC], g_WUh[CC * CC], g_WUl[CC * CC];
__device__ bf16 g_Xth[BATCH * NN * CC], g_Xtl[BATCH * NN * CC];
__device__ bf16 g_Hh[BATCH * CC * NN], g_Hl[BATCH * CC * NN];
__device__ bf16 g_Hth[BATCH * NN * CC], g_Htl[BATCH * NN * CC];
__device__ bf16 g_H2h[BATCH * NN * CC], g_H2l[BATCH * NN * CC];
__device__ bf16 g_cTh[BATCH * RR * NN], g_cTl[BATCH * RR * NN];
__device__ bf16 g_Ch[BATCH * NN * RR], g_Cl[BATCH * NN * RR];
__device__ bf16 g_bTh[BATCH * RR * CC], g_bTl[BATCH * RR * CC];
__device__ bf16 g_Wbh[BATCH * CC * RR], g_Wbl[BATCH * CC * RR];

// ============ cp.async 3-stage mma.sync GEMM (NPROD=3: bf16x3, NPROD=1: single bf16) ============
// D[m][n'] = sum_k A[m][k]*B[n'][k]. 8 warps 4(M)x2(N), tile 128xTN, K-chunk 32, 3 stages.
// EPI 0: fp32 (split-K). 1: lower. 2: cheese. 3: upper. 4: softmax init. 5: coef MU.
template <int TN, int SPLITK, int EPI, int NPROD>
__global__ void __launch_bounds__(256) k_mma(
    const bf16* __restrict__ Ahi, const bf16* __restrict__ Alo, size_t aB, int aS,
    const bf16* __restrict__ Bhi, const bf16* __restrict__ Blo, size_t bB, int bS,
    int kLen,
    float* __restrict__ outF, size_t oB, int oS,
    bf16* __restrict__ oHi, bf16* __restrict__ oLo, const float* __restrict__ bias,
    bf16* __restrict__ tHi, bf16* __restrict__ tLo,
    const float* __restrict__ Xres, const float* __restrict__ sH, const float* __restrict__ sS,
    float* __restrict__ coefF, const float* __restrict__ btbP)
{
    extern __shared__ char smem[];
    constexpr int NF = TN / 16;
    constexpr int WN = TN / 2;
    constexpr int SW = TN + 1;
    constexpr int HTN = TN / 2;
    constexpr int CSH2 = (TN == 128) ? 6 : 5;
    constexpr int SS = (256 + 2 * TN) * 40;    // bf16 elems per stage
    bf16* sb16 = (bf16*)smem;
    float* stage = (float*)smem;
    uint32_t smb = smem_u32(smem);

    int tid = threadIdx.x, lane = tid & 31, wid = tid >> 5;
    int wm = wid >> 1, wn = wid & 1;
    int b = blockIdx.z;
    int ks = (SPLITK > 1) ? blockIdx.x : 0;
    int n0 = (SPLITK > 1) ? 0 : blockIdx.x * TN;
    int m0 = blockIdx.y * 128;

    const bf16* A0 = Ahi + (size_t)b * aB + (size_t)m0 * aS + ks * kLen;
    const bf16* A1 = (NPROD == 3) ? Alo + (size_t)b * aB + (size_t)m0 * aS + ks * kLen : nullptr;
    const bf16* B0 = Bhi + (size_t)b * bB + (size_t)n0 * bS + ks * kLen;
    const bf16* B1 = (NPROD == 3) ? Blo + (size_t)b * bB + (size_t)n0 * bS + ks * kLen : nullptr;

    float c[2][NF][4];
    #pragma unroll
    for (int i = 0; i < 2; i++)
        #pragma unroll
        for (int j = 0; j < NF; j++)
            #pragma unroll
            for (int q = 0; q < 4; q++) c[i][j][q] = 0.f;

    auto aoff = [&](int st, int pl, int r, int col) { return st * SS + pl * (128 * 40) + r * 40 + col; };
    auto boff = [&](int st, int pl, int r, int col) { return st * SS + 256 * 40 + pl * (TN * 40) + r * 40 + col; };

    auto loadst = [&](int st, int koff) {
        #pragma unroll
        for (int i = tid; i < 512; i += 256) {
            int r = i >> 2, q = i & 3;
            size_t o = (size_t)r * aS + koff + q * 8;
            cpa16ca(smb + 2u * aoff(st, 0, r, q * 8), A0 + o);
            if (NPROD == 3) cpa16ca(smb + 2u * aoff(st, 1, r, q * 8), A1 + o);
        }
        #pragma unroll
        for (int i = tid; i < TN * 4; i += 256) {
            int r = i >> 2, q = i & 3;
            size_t o = (size_t)r * bS + koff + q * 8;
            cpa16(smb + 2u * boff(st, 0, r, q * 8), B0 + o);
            if (NPROD == 3) cpa16(smb + 2u * boff(st, 1, r, q * 8), B1 + o);
        }
    };
    auto compute = [&](int st, float (*acc)[NF][4]) {
        #pragma unroll
        for (int kk = 0; kk < 32; kk += 16) {
            uint32_t a[2][2][4];
            #pragma unroll
            for (int pl = 0; pl < ((NPROD == 3) ? 2 : 1); pl++)
                #pragma unroll
                for (int mf = 0; mf < 2; mf++)
                    ldsm4(a[pl][mf], smb + 2u * aoff(st, pl, wm * 32 + mf * 16 + (lane & 15),
                                                     kk + (lane >> 4) * 8));
            #pragma unroll
            for (int nf2 = 0; nf2 < NF / 2; nf2++) {
                uint32_t bq0[4];
                ldsm4(bq0, smb + 2u * boff(st, 0, wn * WN + nf2 * 16 + (lane & 15),
                                           kk + (lane >> 4) * 8));
                uint32_t bh[2][2] = {{bq0[0], bq0[2]}, {bq0[1], bq0[3]}};
                if (NPROD == 3) {
                    uint32_t bq1[4];
                    ldsm4(bq1, smb + 2u * boff(st, 1, wn * WN + nf2 * 16 + (lane & 15),
                                               kk + (lane >> 4) * 8));
                    uint32_t bl[2][2] = {{bq1[0], bq1[2]}, {bq1[1], bq1[3]}};
                    #pragma unroll
                    for (int hf = 0; hf < 2; hf++)
                        #pragma unroll
                        for (int mf = 0; mf < 2; mf++) {
                            mma16816(acc[mf][2 * nf2 + hf], a[0][mf], bh[hf]);
                            mma16816(acc[mf][2 * nf2 + hf], a[0][mf], bl[hf]);
                            mma16816(acc[mf][2 * nf2 + hf], a[1][mf], bh[hf]);
                        }
                } else {
                    #pragma unroll
                    for (int hf = 0; hf < 2; hf++)
                        #pragma unroll
                        for (int mf = 0; mf < 2; mf++)
                            mma16816(acc[mf][2 * nf2 + hf], a[0][mf], bh[hf]);
                }
            }
        }
    };

    int nch = kLen / 32;
    #pragma unroll
    for (int s = 0; s < 2; s++) {
        if (s < nch) loadst(s, s * 32);
        CP_COMMIT();
    }
    for (int ch = 0; ch < nch; ch++) {
        CP_WAIT1();
        __syncthreads();
        if (ch + 2 < nch) loadst((ch + 2) % 3, (ch + 2) * 32);
        CP_COMMIT();
        compute(ch % 3, c);
    }
    __syncthreads();

    // ---- EPI5: den = coef @ btb on tensor cores (stages 0,1) ----
    float c2[2][NF][4];
    if (EPI == 5) {
        #pragma unroll
        for (int i = 0; i < 2; i++)
            #pragma unroll
            for (int j = 0; j < NF; j++)
                #pragma unroll
                for (int q = 0; q < 4; q++) c2[i][j][q] = 0.f;
        for (int i = tid; i < 1024; i += 256) {
            int r = i >> 3, q = i & 7, st = q >> 2, qq = q & 3;
            size_t gi = ((size_t)b * NN + m0 + r) * RR + st * 32 + qq * 8;
            *(uint4*)&sb16[aoff(st, 0, r, qq * 8)] = *(const uint4*)(oHi + gi);
            if (NPROD == 3)
                *(uint4*)&sb16[aoff(st, 1, r, qq * 8)] = *(const uint4*)(oLo + gi);
        }
        // btb: reduce 8 k-partials, convert to bf16 in smem B region
        for (int i = tid; i < 4096; i += 256) {
            int r = i >> 6, ck = i & 63;
            float v = 0.f;
            #pragma unroll
            for (int k = 0; k < 8; k++) v += btbP[((size_t)(b * 8 + k)) * 4096 + i];
            int st = ck >> 5, cc = ck & 31;
            bf16 h = F2B(v);
            sb16[boff(st, 0, r, cc)] = h;
            if (NPROD == 3) sb16[boff(st, 1, r, cc)] = F2B(v - B2F(h));
        }
        __syncthreads();
        compute(0, c2);
        compute(1, c2);
        __syncthreads();
    }

    // ---- stage accumulators ----
    float* sX = stage;
    float* sD = stage + 128 * 65;
    #pragma unroll
    for (int mf = 0; mf < 2; mf++)
        #pragma unroll
        for (int nf = 0; nf < NF; nf++) {
            int row = wm * 32 + mf * 16 + (lane >> 2);
            int col = wn * WN + nf * 8 + (lane & 3) * 2;
            if (EPI >= 4) {
                sX[row * 65 + col] = c[mf][nf][0];       sX[row * 65 + col + 1] = c[mf][nf][1];
                sX[(row + 8) * 65 + col] = c[mf][nf][2]; sX[(row + 8) * 65 + col + 1] = c[mf][nf][3];
                if (EPI == 5) {
                    sD[row * 65 + col] = c2[mf][nf][0];       sD[row * 65 + col + 1] = c2[mf][nf][1];
                    sD[(row + 8) * 65 + col] = c2[mf][nf][2]; sD[(row + 8) * 65 + col + 1] = c2[mf][nf][3];
                }
            } else {
                stage[row * SW + col] = c[mf][nf][0];       stage[row * SW + col + 1] = c[mf][nf][1];
                stage[(row + 8) * SW + col] = c[mf][nf][2]; stage[(row + 8) * SW + col + 1] = c[mf][nf][3];
            }
        }
    __syncthreads();

    if (EPI == 0) {
        for (int i = tid; i < 128 * HTN; i += 256) {
            int row = i >> CSH2, c2i = (i & (HTN - 1)) * 2;
            size_t idx = (size_t)(b * SPLITK + ks) * oB + (size_t)(m0 + row) * oS + n0 + c2i;
            *(float2*)(outF + idx) = make_float2(stage[row * SW + c2i], stage[row * SW + c2i + 1]);
        }
    } else if (EPI == 1) {
        for (int i = tid; i < 128 * HTN; i += 256) {
            int row = i >> CSH2, c2i = (i & (HTN - 1)) * 2;
            float bv = bias[m0 + row];
            float v0 = fmaxf(stage[row * SW + c2i] + bv, 0.f);
            float v1 = fmaxf(stage[row * SW + c2i + 1] + bv, 0.f);
            size_t idx = (size_t)b * (CC * NN) + (size_t)(m0 + row) * NN + n0 + c2i;
            store_pair2(oHi, oLo, idx, v0, v1);
            stage[row * SW + c2i] = v0; stage[row * SW + c2i + 1] = v1;
        }
        __syncthreads();
        for (int i = tid; i < 64 * TN; i += 256) {
            int col = i >> 6, r2 = (i & 63) * 2;
            float v0 = stage[r2 * SW + col], v1 = stage[(r2 + 1) * SW + col];
            size_t idx = (size_t)b * (NN * CC) + (size_t)(n0 + col) * CC + m0 + r2;
            store_pair2(tHi, tLo, idx, v0, v1);
        }
    } else if (EPI == 2) {
        for (int i = tid; i < 128 * HTN; i += 256) {
            int row = i >> CSH2, c2i = (i & (HTN - 1)) * 2;
            float v0 = fmaxf(stage[row * SW + c2i] + bias[n0 + c2i], 0.f);
            float v1 = fmaxf(stage[row * SW + c2i + 1] + bias[n0 + c2i + 1], 0.f);
            size_t idx = (size_t)b * (NN * CC) + (size_t)(m0 + row) * CC + n0 + c2i;
            store_pair2(oHi, oLo, idx, v0, v1);
        }
    } else if (EPI == 3) {
        float a = sH[0], s = sS[0];
        for (int i = tid; i < 128 * HTN; i += 256) {
            int row = i >> CSH2, c2i = (i & (HTN - 1)) * 2;
            size_t idx = (size_t)b * oB + (size_t)(m0 + row) * oS + n0 + c2i;
            float2 xv = *(const float2*)(Xres + idx);
            *(float2*)(outF + idx) = make_float2(
                fmaxf(a * stage[row * SW + c2i] + s * xv.x, 0.f),
                fmaxf(a * stage[row * SW + c2i + 1] + s * xv.y, 0.f));
        }
    } else if (EPI == 4) {
        if (tid < 128) {
            float mx = -1e30f;
            for (int cc2 = 0; cc2 < 64; cc2++) mx = fmaxf(mx, sX[tid * 65 + cc2]);
            float s = 0.f;
            for (int cc2 = 0; cc2 < 64; cc2++) {
                float e = expf(sX[tid * 65 + cc2] - mx);
                sX[tid * 65 + cc2] = e; s += e;
            }
            float inv = 1.0f / s;
            for (int cc2 = 0; cc2 < 64; cc2++) sX[tid * 65 + cc2] *= inv;
        }
        __syncthreads();
        for (int i = tid; i < 4096; i += 256) {
            int row = i >> 5, c2i = (i & 31) * 2;
            float v0 = sX[row * 65 + c2i], v1 = sX[row * 65 + c2i + 1];
            size_t gi = ((size_t)b * NN + m0 + row) * RR + c2i;
            *(float2*)(coefF + gi) = make_float2(v0, v1);
            store_pair2(oHi, oLo, gi, v0, v1);
        }
    } else {  // EPI == 5
        for (int i = tid; i < 4096; i += 256) {
            int row = i >> 5, c2i = (i & 31) * 2;
            size_t gi = ((size_t)b * NN + m0 + row) * RR + c2i;
            float2 cv = *(const float2*)(coefF + gi);
            float v0 = cv.x * sX[row * 65 + c2i] / (sD[row * 65 + c2i] + EPSV);
            float v1 = cv.y * sX[row * 65 + c2i + 1] / (sD[row * 65 + c2i + 1] + EPSV);
            *(float2*)(coefF + gi) = make_float2(v0, v1);
            store_pair2(oHi, oLo, gi, v0, v1);
            sX[row * 65 + c2i] = v0; sX[row * 65 + c2i + 1] = v1;
        }
        __syncthreads();
        for (int i = tid; i < 4096; i += 256) {
            int col = i >> 6, r2 = (i & 63) * 2;
            float v0 = sX[r2 * 65 + col], v1 = sX[(r2 + 1) * 65 + col];
            size_t gi = (size_t)b * RR * NN + (size_t)col * NN + m0 + r2;
            store_pair2(tHi, tLo, gi, v0, v1);
        }
    }
}

// -------- SIMT helpers --------
__global__ void k_norm_bases(const float* __restrict__ b0) {
    int b = blockIdx.x;
    __shared__ float part[8][64];
    __shared__ float inv[64];
    int r = threadIdx.x & 63, g = threadIdx.x >> 6;
    float s = 0.f;
    for (int d = g; d < CC; d += 8) { float v = b0[((size_t)b * CC + d) * RR + r]; s += v * v; }
    part[g][r] = s;
    __syncthreads();
    if (g == 0) {
        float t = 0.f;
        #pragma unroll
        for (int i = 0; i < 8; i++) t += part[i][r];
        inv[r] = 1.0f / fmaxf(sqrtf(t), 1e-12f);
    }
    __syncthreads();
    for (int d = g; d < CC; d += 8) {
        size_t i = ((size_t)b * CC + d) * RR + r;
        g_bases[i] = b0[i] * inv[r];
    }
}

__global__ void __launch_bounds__(256) k_ata(const float* __restrict__ Mb, size_t mS,
                                             int kPB, float* __restrict__ out, int nsp) {
    int sp = blockIdx.x, b = blockIdx.y;
    const float* M = Mb + (size_t)b * mS + (size_t)sp * kPB * RR;
    __shared__ float S[64][64];
    int t = threadIdx.x, rI = (t & 15) * 4, sI = (t >> 4) * 4;
    float acc[4][4] = {};
    for (int k0 = 0; k0 < kPB; k0 += 64) {
        #pragma unroll
        for (int p = 0; p < 4; p++) {
            int kr = (t >> 4) + p * 16;
            *(float4*)&S[kr][(t & 15) * 4] = *(const float4*)(M + (size_t)(k0 + kr) * RR + (t & 15) * 4);
        }
        __syncthreads();
        #pragma unroll
        for (int k = 0; k < 64; k++) {
            float4 av = *(const float4*)&S[k][rI];
            float4 bv = *(const float4*)&S[k][sI];
            float a[4] = {av.x, av.y, av.z, av.w}, bb[4] = {bv.x, bv.y, bv.z, bv.w};
            #pragma unroll
            for (int i = 0; i < 4; i++)
                #pragma unroll
                for (int j = 0; j < 4; j++) acc[i][j] = fmaf(a[i], bb[j], acc[i][j]);
        }
        __syncthreads();
    }
    float* o = out + ((size_t)b * nsp + sp) * (RR * RR);
    #pragma unroll
    for (int i = 0; i < 4; i++)
        *(float4*)&o[(size_t)(rI + i) * RR + sI] =
            make_float4(acc[i][0], acc[i][1], acc[i][2], acc[i][3]);
}

// bases update: reduce ctcp(16)+xcp(8), MU, write bases + coalesced bT pairs
__global__ void __launch_bounds__(256) k_bup() {
    int b = blockIdx.y, d0 = blockIdx.x * 64;
    __shared__ float ctc[64][65];
    __shared__ float bs[64][65];
    __shared__ float xcs[64][65];
    int t = threadIdx.x;
    for (int i = t; i < 4096; i += 256) {
        float v = 0.f;
        #pragma unroll 4
        for (int k = 0; k < 16; k++) v += g_ctcp[((size_t)(b * 16 + k)) * 4096 + i];
        ctc[i >> 6][i & 63] = v;
    }
    for (int i = t; i < 4096; i += 256) {
        int d = i >> 6, r = i & 63;
        bs[d][r] = g_bases[((size_t)b * CC + d0 + d) * RR + r];
        float v = 0.f;
        #pragma unroll
        for (int k = 0; k < 8; k++) v += g_xcp[((size_t)(b * 8 + k) * CC + d0 + d) * RR + r];
        xcs[d][r] = v;
    }
    __syncthreads();
    for (int i = t; i < 4096; i += 256) {
        int d = i >> 6, r = i & 63;
        float den = EPSV;
        #pragma unroll
        for (int s = 0; s < 64; s++) den = fmaf(bs[d][s], ctc[s][r], den);
        float v = bs[d][r] * xcs[d][r] / den;
        g_bases[((size_t)b * CC + d0 + d) * RR + r] = v;
        xcs[d][r] = v;   // stage updated bases
    }
    __syncthreads();
    for (int i = t; i < 2048; i += 256) {
        int r = i >> 5, d2 = (i & 31) * 2;
        size_t ti = ((size_t)b * RR + r) * CC + d0 + d2;
        store_pair2(g_bTh, g_bTl, ti, xcs[d2][r], xcs[d2 + 1][r]);
    }
}

__global__ void k_cvt(const float* __restrict__ s, bf16* __restrict__ hi, bf16* __restrict__ lo, int n) {
    int i = (blockIdx.x * 256 + threadIdx.x) * 2;
    if (i >= n) return;
    float2 v = *(const float2*)(s + i);
    store_pair2(hi, lo, i, v.x, v.y);
}

__global__ void k_tcvt(const float* __restrict__ src, bf16* __restrict__ dh, bf16* __restrict__ dl,
                       int rows, int cols) {
    __shared__ float t[32][33];
    int b = blockIdx.z;
    size_t sb = (size_t)b * rows * cols;
    int r0 = blockIdx.y * 32, c0 = blockIdx.x * 32;
    int tx = threadIdx.x & 31, ty = threadIdx.x >> 5;
    #pragma unroll
    for (int p = 0; p < 4; p++)
        t[ty + p * 8][tx] = src[sb + (size_t)(r0 + ty + p * 8) * cols + c0 + tx];
    __syncthreads();
    int tx2 = (threadIdx.x & 15) * 2, tyy = threadIdx.x >> 4;
    #pragma unroll
    for (int p = 0; p < 2; p++) {
        int cr = tyy + p * 16;
        size_t o = sb + (size_t)(c0 + cr) * rows + r0 + tx2;
        store_pair2(dh, dl, o, t[tx2][cr], t[tx2 + 1][cr]);
    }
}

__global__ void __launch_bounds__(256) k_wb(const float* __restrict__ Wc) {
    int b = blockIdx.y, m0 = blockIdx.x * 64;
    __shared__ float Ws[64][65];
    __shared__ float Bs[64][64];
    int t = threadIdx.x, mI = (t & 15) * 4, rI = (t >> 4) * 4;
    float acc[4][4] = {};
    for (int k0 = 0; k0 < CC; k0 += 64) {
        #pragma unroll
        for (int p = 0; p < 16; p++) {
            int lin = t + p * 256;
            Ws[lin >> 6][lin & 63] = Wc[(size_t)(m0 + (lin >> 6)) * CC + k0 + (lin & 63)];
            Bs[lin >> 6][lin & 63] = g_bases[((size_t)b * CC + k0 + (lin >> 6)) * RR + (lin & 63)];
        }
        __syncthreads();
        #pragma unroll
        for (int k = 0; k < 64; k++)
            #pragma unroll
            for (int i = 0; i < 4; i++)
                #pragma unroll
                for (int j = 0; j < 4; j++)
                    acc[i][j] = fmaf(Ws[mI + i][k], Bs[k][rI + j], acc[i][j]);
        __syncthreads();
    }
    #pragma unroll
    for (int i = 0; i < 4; i++)
        #pragma unroll
        for (int j = 0; j < 2; j++) {
            size_t idx = ((size_t)b * CC + m0 + mI + i) * RR + rI + j * 2;
            store_pair2(g_Wbh, g_Wbl, idx, acc[i][j * 2], acc[i][j * 2 + 1]);
        }
}

#define GSA(p, s) cudaGetSymbolAddress((void**)&p, s)

extern "C" void kernel_launch(void* const* d_in, const int* in_sizes, int n_in,
                              void* d_out, int out_size) {
    const float* x        = (const float*)d_in[0];
    const float* bases0   = (const float*)d_in[1];
    const float* w_lower  = (const float*)d_in[2];
    const float* b_lower  = (const float*)d_in[3];
    const float* w_cheese = (const float*)d_in[4];
    const float* b_cheese = (const float*)d_in[5];
    const float* w_upper  = (const float*)d_in[6];
    const float* c_short  = (const float*)d_in[7];
    const float* c_ham    = (const float*)d_in[8];
    float* out = (float*)d_out;

    float *bases, *coef, *btbp, *ctcp, *xcp;
    GSA(bases, g_bases); GSA(coef, g_coef); GSA(btbp, g_btbp); GSA(ctcp, g_ctcp); GSA(xcp, g_xcp);
    bf16 *WLh, *WLl, *WUh, *WUl, *Xth, *Xtl, *Hh, *Hl, *Hth, *Htl, *H2h, *H2l;
    bf16 *cTh, *cTl, *Ch, *Cl, *bTh, *bTl, *Wbh, *Wbl;
    GSA(WLh, g_WLh); GSA(WLl, g_WLl); GSA(WUh, g_WUh); GSA(WUl, g_WUl);
    GSA(Xth, g_Xth); GSA(Xtl, g_Xtl); GSA(Hh, g_Hh); GSA(Hl, g_Hl);
    GSA(Hth, g_Hth); GSA(Htl, g_Htl); GSA(H2h, g_H2h); GSA(H2l, g_H2l);
    GSA(cTh, g_cTh); GSA(cTl, g_cTl); GSA(Ch, g_Ch); GSA(Cl, g_Cl);
    GSA(bTh, g_bTh); GSA(bTl, g_bTl); GSA(Wbh, g_Wbh); GSA(Wbl, g_Wbl);

    const int SM128 = 3 * (256 + 256) * 40 * 2;  // 122880
    const int SM64  = 3 * (256 + 128) * 40 * 2;  // 92160
    cudaFuncSetAttribute((void*)k_mma<128, 1, 1, 3>, cudaFuncAttributeMaxDynamicSharedMemorySize, SM128);
    cudaFuncSetAttribute((void*)k_mma<128, 1, 2, 3>, cudaFuncAttributeMaxDynamicSharedMemorySize, SM128);
    cudaFuncSetAttribute((void*)k_mma<128, 1, 3, 3>, cudaFuncAttributeMaxDynamicSharedMemorySize, SM128);
    cudaFuncSetAttribute((void*)k_mma<64, 1, 4, 1>,  cudaFuncAttributeMaxDynamicSharedMemorySize, SM64);
    cudaFuncSetAttribute((void*)k_mma<64, 1, 5, 1>,  cudaFuncAttributeMaxDynamicSharedMemorySize, SM64);
    cudaFuncSetAttribute((void*)k_mma<64, 8, 0, 1>,  cudaFuncAttributeMaxDynamicSharedMemorySize, SM64);

    k_cvt<<<(CC * CC / 2 + 255) / 256, 256>>>(w_lower, WLh, WLl, CC * CC);
    k_cvt<<<(CC * CC / 2 + 255) / 256, 256>>>(w_upper, WUh, WUl, CC * CC);
    k_tcvt<<<dim3(NN / 32, CC / 32, BATCH), 256>>>(x, Xth, Xtl, CC, NN);
    k_norm_bases<<<BATCH, 512>>>(bases0);
    k_tcvt<<<dim3(RR / 32, CC / 32, BATCH), 256>>>(bases, bTh, bTl, CC, RR);

    // H = relu(WL @ X + b) -> H pairs + Ht pairs   (bf16x3)
    k_mma<128, 1, 1, 3><<<dim3(32, 4, BATCH), 256, SM128>>>(
        WLh, WLl, 0, CC, Xth, Xtl, (size_t)NN * CC, CC, CC,
        nullptr, 0, 0, Hh, Hl, b_lower, Hth, Htl,
        nullptr, nullptr, nullptr, nullptr, nullptr);

    // coef = softmax(Ht @ bT) -> coef fp32 + Ch/Cl pairs   (single bf16)
    k_mma<64, 1, 4, 1><<<dim3(1, 32, BATCH), 256, SM64>>>(
        Hth, Htl, (size_t)NN * CC, CC, bTh, bTl, (size_t)RR * CC, CC, CC,
        nullptr, 0, 0, Ch, Cl, nullptr, nullptr, nullptr,
        nullptr, nullptr, nullptr, coef, nullptr);

    for (int it = 0; it <= NSTEPS; it++) {
        // btb partials (8 k-splits of 64 rows)
        k_ata<<<dim3(8, BATCH), 256>>>(bases, (size_t)CC * RR, 64, btbp, 8);
        // coef MU: xtb GEMM + den GEMM + update -> coef + Ch/Cl + cT pairs   (single bf16)
        k_mma<64, 1, 5, 1><<<dim3(1, 32, BATCH), 256, SM64>>>(
            Hth, Htl, (size_t)NN * CC, CC, bTh, bTl, (size_t)RR * CC, CC, CC,
            nullptr, 0, 0, Ch, Cl, nullptr, cTh, cTl,
            nullptr, nullptr, nullptr, coef, btbp);
        if (it == NSTEPS) break;  // last = differentiable refinement, no bases update
        k_ata<<<dim3(16, BATCH), 256>>>(coef, (size_t)NN * RR, 256, ctcp, 16);
        // xc = H @ cT  (single bf16, split-K 8)
        k_mma<64, 8, 0, 1><<<dim3(8, 4, BATCH), 256, SM64>>>(
            Hh, Hl, (size_t)CC * NN, NN, cTh, cTl, (size_t)RR * NN, NN, NN / 8,
            xcp, (size_t)CC * RR, RR, nullptr, nullptr, nullptr, nullptr, nullptr,
            nullptr, nullptr, nullptr, nullptr, nullptr);
        k_bup<<<dim3(8, BATCH), 256>>>();   // bases MU + bT pairs
    }

    // fused cheese: H2[n][c2] = relu(coef @ (Wc@bases)^T + b_cheese)   (bf16x3)
    k_wb<<<dim3(CC / 64, BATCH), 256>>>(w_cheese);
    k_mma<128, 1, 2, 3><<<dim3(4, 32, BATCH), 256, SM128>>>(
        Ch, Cl, (size_t)NN * RR, RR, Wbh, Wbl, (size_t)CC * RR, RR, RR,
        nullptr, 0, 0, H2h, H2l, b_cheese, nullptr, nullptr,
        nullptr, nullptr, nullptr, nullptr, nullptr);
    // out = relu(c_ham * (WU @ H2) + c_short * x)   (bf16x3)
    k_mma<128, 1, 3, 3><<<dim3(32, 4, BATCH), 256, SM128>>>(
        WUh, WUl, 0, CC, H2h, H2l, (size_t)NN * CC, CC, CC,
        out, (size_t)CC * NN, NN, nullptr, nullptr, nullptr, nullptr, nullptr,
        x, c_ham, c_short, nullptr, nullptr);
    (void)in_sizes; (void)n_in; (void)out_size;
}

// round 13
// speedup vs baseline: 1.4221x; 1.4221x over previous
#include <cuda_runtime.h>
#include <cuda_bf16.h>
#include <cstdint>
#include <math.h>

#define BATCH 8
#define CC 512
#define NN 4096
#define RR 64
#define EPSV 1e-6f
#define NSTEPS 6
typedef __nv_bfloat16 bf16;
#define F2B(v) __float2bfloat16(v)
#define B2F(v) __bfloat162float(v)

__device__ __forceinline__ uint32_t smem_u32(const void* p) {
    uint32_t a;
    asm("{ .reg .u64 t; cvta.to.shared.u64 t, %1; cvt.u32.u64 %0, t; }" : "=r"(a) : "l"(p));
    return a;
}
__device__ __forceinline__ void cpa16(uint32_t s, const void* g) {
    asm volatile("cp.async.cg.shared.global [%0], [%1], 16;" :: "r"(s), "l"(g));
}
__device__ __forceinline__ void cpa16ca(uint32_t s, const void* g) {
    asm volatile("cp.async.ca.shared.global [%0], [%1], 16;" :: "r"(s), "l"(g));
}
#define CP_COMMIT() asm volatile("cp.async.commit_group;" ::: "memory")
#define CP_WAIT1()  asm volatile("cp.async.wait_group 1;" ::: "memory")
__device__ __forceinline__ void ldsm4(uint32_t* d, uint32_t addr) {
    asm volatile("ldmatrix.sync.aligned.m8n8.x4.shared.b16 {%0,%1,%2,%3}, [%4];"
        : "=r"(d[0]), "=r"(d[1]), "=r"(d[2]), "=r"(d[3]) : "r"(addr));
}
__device__ __forceinline__ void mma16816(float* c, const uint32_t* a, const uint32_t* b) {
    asm volatile("mma.sync.aligned.m16n8k16.row.col.f32.bf16.bf16.f32 "
        "{%0,%1,%2,%3}, {%4,%5,%6,%7}, {%8,%9}, {%0,%1,%2,%3};"
        : "+f"(c[0]), "+f"(c[1]), "+f"(c[2]), "+f"(c[3])
        : "r"(a[0]), "r"(a[1]), "r"(a[2]), "r"(a[3]), "r"(b[0]), "r"(b[1]));
}
__device__ __forceinline__ void store_pair2(bf16* hi, bf16* lo, size_t idx, float v0, float v1) {
    bf16 h0 = F2B(v0), h1 = F2B(v1);
    *(__nv_bfloat162*)(hi + idx) = __halves2bfloat162(h0, h1);
    *(__nv_bfloat162*)(lo + idx) =
        __halves2bfloat162(F2B(v0 - B2F(h0)), F2B(v1 - B2F(h1)));
}

// -------- scratch --------
__device__ float g_bases[BATCH * CC * RR];
__device__ float g_coef[BATCH * NN * RR];
__device__ float g_btbp[BATCH * 8 * RR * RR];
__device__ float g_ctcp[BATCH * 16 * RR * RR];
__device__ float g_xcp[BATCH * 8 * CC * RR];
__device__ bf16 g_WLh[CC * CC], g_WLl[CC * CC], g_WUh[CC * CC], g_WUl[CC * CC];
__device__ bf16 g_Xth[BATCH * NN * CC], g_Xtl[BATCH * NN * CC];
__device__ bf16 g_Hh[BATCH * CC * NN], g_Hl[BATCH * CC * NN];
__device__ bf16 g_Hth[BATCH * NN * CC], g_Htl[BATCH * NN * CC];
__device__ bf16 g_H2h[BATCH * NN * CC], g_H2l[BATCH * NN * CC];
__device__ bf16 g_cTh[BATCH * RR * NN], g_cTl[BATCH * RR * NN];
__device__ bf16 g_Ch[BATCH * NN * RR], g_Cl[BATCH * NN * RR];
__device__ bf16 g_bTh[BATCH * RR * CC], g_bTl[BATCH * RR * CC];
__device__ bf16 g_Wbh[BATCH * CC * RR], g_Wbl[BATCH * CC * RR];

// ============ cp.async 3-stage mma.sync GEMM (NPROD=3: bf16x3 2-plane, NPROD=1: 1-plane) ============
// D[m][n'] = sum_k A[m][k]*B[n'][k]. 8 warps 4(M)x2(N), tile 128xTN, K-chunk 32, 3 stages.
// EPI 0: fp32 (split-K). 1: lower. 2: cheese. 3: upper. 4: softmax init. 5: coef MU.
template <int TN, int SPLITK, int EPI, int NPROD>
__global__ void __launch_bounds__(256) k_mma(
    const bf16* __restrict__ Ahi, const bf16* __restrict__ Alo, size_t aB, int aS,
    const bf16* __restrict__ Bhi, const bf16* __restrict__ Blo, size_t bB, int bS,
    int kLen,
    float* __restrict__ outF, size_t oB, int oS,
    bf16* __restrict__ oHi, bf16* __restrict__ oLo, const float* __restrict__ bias,
    bf16* __restrict__ tHi, bf16* __restrict__ tLo,
    const float* __restrict__ Xres, const float* __restrict__ sH, const float* __restrict__ sS,
    float* __restrict__ coefF, const float* __restrict__ btbP)
{
    extern __shared__ char smem[];
    constexpr int NF = TN / 16;
    constexpr int WN = TN / 2;
    constexpr int SW = TN + 1;
    constexpr int HTN = TN / 2;
    constexpr int CSH2 = (TN == 128) ? 6 : 5;
    constexpr int P = (NPROD == 3) ? 2 : 1;        // bf16 planes resident in smem
    constexpr int SS = P * (128 + TN) * 40;        // bf16 elems per stage
    bf16* sb16 = (bf16*)smem;
    float* stage = (float*)smem;
    uint32_t smb = smem_u32(smem);

    int tid = threadIdx.x, lane = tid & 31, wid = tid >> 5;
    int wm = wid >> 1, wn = wid & 1;
    int b = blockIdx.z;
    int ks = (SPLITK > 1) ? blockIdx.x : 0;
    int n0 = (SPLITK > 1) ? 0 : blockIdx.x * TN;
    int m0 = blockIdx.y * 128;

    const bf16* A0 = Ahi + (size_t)b * aB + (size_t)m0 * aS + ks * kLen;
    const bf16* A1 = (NPROD == 3) ? Alo + (size_t)b * aB + (size_t)m0 * aS + ks * kLen : nullptr;
    const bf16* B0 = Bhi + (size_t)b * bB + (size_t)n0 * bS + ks * kLen;
    const bf16* B1 = (NPROD == 3) ? Blo + (size_t)b * bB + (size_t)n0 * bS + ks * kLen : nullptr;

    float c[2][NF][4];
    #pragma unroll
    for (int i = 0; i < 2; i++)
        #pragma unroll
        for (int j = 0; j < NF; j++)
            #pragma unroll
            for (int q = 0; q < 4; q++) c[i][j][q] = 0.f;

    auto aoff = [&](int st, int pl, int r, int col) { return st * SS + pl * (128 * 40) + r * 40 + col; };
    auto boff = [&](int st, int pl, int r, int col) { return st * SS + P * (128 * 40) + pl * (TN * 40) + r * 40 + col; };

    auto loadst = [&](int st, int koff) {
        #pragma unroll
        for (int i = tid; i < 512; i += 256) {
            int r = i >> 2, q = i & 3;
            size_t o = (size_t)r * aS + koff + q * 8;
            cpa16ca(smb + 2u * aoff(st, 0, r, q * 8), A0 + o);
            if (NPROD == 3) cpa16ca(smb + 2u * aoff(st, 1, r, q * 8), A1 + o);
        }
        #pragma unroll
        for (int i = tid; i < TN * 4; i += 256) {
            int r = i >> 2, q = i & 3;
            size_t o = (size_t)r * bS + koff + q * 8;
            cpa16(smb + 2u * boff(st, 0, r, q * 8), B0 + o);
            if (NPROD == 3) cpa16(smb + 2u * boff(st, 1, r, q * 8), B1 + o);
        }
    };
    auto compute = [&](int st, float (*acc)[NF][4]) {
        #pragma unroll
        for (int kk = 0; kk < 32; kk += 16) {
            uint32_t a[2][2][4];
            #pragma unroll
            for (int pl = 0; pl < P; pl++)
                #pragma unroll
                for (int mf = 0; mf < 2; mf++)
                    ldsm4(a[pl][mf], smb + 2u * aoff(st, pl, wm * 32 + mf * 16 + (lane & 15),
                                                     kk + (lane >> 4) * 8));
            #pragma unroll
            for (int nf2 = 0; nf2 < NF / 2; nf2++) {
                uint32_t bq0[4];
                ldsm4(bq0, smb + 2u * boff(st, 0, wn * WN + nf2 * 16 + (lane & 15),
                                           kk + (lane >> 4) * 8));
                uint32_t bh[2][2] = {{bq0[0], bq0[2]}, {bq0[1], bq0[3]}};
                if (NPROD == 3) {
                    uint32_t bq1[4];
                    ldsm4(bq1, smb + 2u * boff(st, 1, wn * WN + nf2 * 16 + (lane & 15),
                                               kk + (lane >> 4) * 8));
                    uint32_t bl[2][2] = {{bq1[0], bq1[2]}, {bq1[1], bq1[3]}};
                    #pragma unroll
                    for (int hf = 0; hf < 2; hf++)
                        #pragma unroll
                        for (int mf = 0; mf < 2; mf++) {
                            mma16816(acc[mf][2 * nf2 + hf], a[0][mf], bh[hf]);
                            mma16816(acc[mf][2 * nf2 + hf], a[0][mf], bl[hf]);
                            mma16816(acc[mf][2 * nf2 + hf], a[1][mf], bh[hf]);
                        }
                } else {
                    #pragma unroll
                    for (int hf = 0; hf < 2; hf++)
                        #pragma unroll
                        for (int mf = 0; mf < 2; mf++)
                            mma16816(acc[mf][2 * nf2 + hf], a[0][mf], bh[hf]);
                }
            }
        }
    };

    int nch = kLen / 32;
    #pragma unroll
    for (int s = 0; s < 2; s++) {
        if (s < nch) loadst(s, s * 32);
        CP_COMMIT();
    }
    for (int ch = 0; ch < nch; ch++) {
        CP_WAIT1();
        __syncthreads();
        if (ch + 2 < nch) loadst((ch + 2) % 3, (ch + 2) * 32);
        CP_COMMIT();
        compute(ch % 3, c);
    }
    __syncthreads();

    // ---- EPI5: den = coef @ btb on tensor cores (stages 0,1) ----
    float c2[2][NF][4];
    if (EPI == 5) {
        #pragma unroll
        for (int i = 0; i < 2; i++)
            #pragma unroll
            for (int j = 0; j < NF; j++)
                #pragma unroll
                for (int q = 0; q < 4; q++) c2[i][j][q] = 0.f;
        for (int i = tid; i < 1024; i += 256) {
            int r = i >> 3, q = i & 7, st = q >> 2, qq = q & 3;
            size_t gi = ((size_t)b * NN + m0 + r) * RR + st * 32 + qq * 8;
            *(uint4*)&sb16[aoff(st, 0, r, qq * 8)] = *(const uint4*)(oHi + gi);
            if (NPROD == 3)
                *(uint4*)&sb16[aoff(st, 1, r, qq * 8)] = *(const uint4*)(oLo + gi);
        }
        // btb: reduce 8 k-partials, convert to bf16 in smem B region
        for (int i = tid; i < 4096; i += 256) {
            int r = i >> 6, ck = i & 63;
            float v = 0.f;
            #pragma unroll
            for (int k = 0; k < 8; k++) v += btbP[((size_t)(b * 8 + k)) * 4096 + i];
            int st = ck >> 5, cc = ck & 31;
            bf16 h = F2B(v);
            sb16[boff(st, 0, r, cc)] = h;
            if (NPROD == 3) sb16[boff(st, 1, r, cc)] = F2B(v - B2F(h));
        }
        __syncthreads();
        compute(0, c2);
        compute(1, c2);
        __syncthreads();
    }

    // ---- stage accumulators ----
    float* sX = stage;
    float* sD = stage + 128 * 65;
    #pragma unroll
    for (int mf = 0; mf < 2; mf++)
        #pragma unroll
        for (int nf = 0; nf < NF; nf++) {
            int row = wm * 32 + mf * 16 + (lane >> 2);
            int col = wn * WN + nf * 8 + (lane & 3) * 2;
            if (EPI >= 4) {
                sX[row * 65 + col] = c[mf][nf][0];       sX[row * 65 + col + 1] = c[mf][nf][1];
                sX[(row + 8) * 65 + col] = c[mf][nf][2]; sX[(row + 8) * 65 + col + 1] = c[mf][nf][3];
                if (EPI == 5) {
                    sD[row * 65 + col] = c2[mf][nf][0];       sD[row * 65 + col + 1] = c2[mf][nf][1];
                    sD[(row + 8) * 65 + col] = c2[mf][nf][2]; sD[(row + 8) * 65 + col + 1] = c2[mf][nf][3];
                }
            } else {
                stage[row * SW + col] = c[mf][nf][0];       stage[row * SW + col + 1] = c[mf][nf][1];
                stage[(row + 8) * SW + col] = c[mf][nf][2]; stage[(row + 8) * SW + col + 1] = c[mf][nf][3];
            }
        }
    __syncthreads();

    if (EPI == 0) {
        for (int i = tid; i < 128 * HTN; i += 256) {
            int row = i >> CSH2, c2i = (i & (HTN - 1)) * 2;
            size_t idx = (size_t)(b * SPLITK + ks) * oB + (size_t)(m0 + row) * oS + n0 + c2i;
            *(float2*)(outF + idx) = make_float2(stage[row * SW + c2i], stage[row * SW + c2i + 1]);
        }
    } else if (EPI == 1) {
        for (int i = tid; i < 128 * HTN; i += 256) {
            int row = i >> CSH2, c2i = (i & (HTN - 1)) * 2;
            float bv = bias[m0 + row];
            float v0 = fmaxf(stage[row * SW + c2i] + bv, 0.f);
            float v1 = fmaxf(stage[row * SW + c2i + 1] + bv, 0.f);
            size_t idx = (size_t)b * (CC * NN) + (size_t)(m0 + row) * NN + n0 + c2i;
            store_pair2(oHi, oLo, idx, v0, v1);
            stage[row * SW + c2i] = v0; stage[row * SW + c2i + 1] = v1;
        }
        __syncthreads();
        for (int i = tid; i < 64 * TN; i += 256) {
            int col = i >> 6, r2 = (i & 63) * 2;
            float v0 = stage[r2 * SW + col], v1 = stage[(r2 + 1) * SW + col];
            size_t idx = (size_t)b * (NN * CC) + (size_t)(n0 + col) * CC + m0 + r2;
            store_pair2(tHi, tLo, idx, v0, v1);
        }
    } else if (EPI == 2) {
        for (int i = tid; i < 128 * HTN; i += 256) {
            int row = i >> CSH2, c2i = (i & (HTN - 1)) * 2;
            float v0 = fmaxf(stage[row * SW + c2i] + bias[n0 + c2i], 0.f);
            float v1 = fmaxf(stage[row * SW + c2i + 1] + bias[n0 + c2i + 1], 0.f);
            size_t idx = (size_t)b * (NN * CC) + (size_t)(m0 + row) * CC + n0 + c2i;
            store_pair2(oHi, oLo, idx, v0, v1);
        }
    } else if (EPI == 3) {
        float a = sH[0], s = sS[0];
        for (int i = tid; i < 128 * HTN; i += 256) {
            int row = i >> CSH2, c2i = (i & (HTN - 1)) * 2;
            size_t idx = (size_t)b * oB + (size_t)(m0 + row) * oS + n0 + c2i;
            float2 xv = *(const float2*)(Xres + idx);
            *(float2*)(outF + idx) = make_float2(
                fmaxf(a * stage[row * SW + c2i] + s * xv.x, 0.f),
                fmaxf(a * stage[row * SW + c2i + 1] + s * xv.y, 0.f));
        }
    } else if (EPI == 4) {
        if (tid < 128) {
            float mx = -1e30f;
            for (int cc2 = 0; cc2 < 64; cc2++) mx = fmaxf(mx, sX[tid * 65 + cc2]);
            float s = 0.f;
            for (int cc2 = 0; cc2 < 64; cc2++) {
                float e = expf(sX[tid * 65 + cc2] - mx);
                sX[tid * 65 + cc2] = e; s += e;
            }
            float inv = 1.0f / s;
            for (int cc2 = 0; cc2 < 64; cc2++) sX[tid * 65 + cc2] *= inv;
        }
        __syncthreads();
        for (int i = tid; i < 4096; i += 256) {
            int row = i >> 5, c2i = (i & 31) * 2;
            float v0 = sX[row * 65 + c2i], v1 = sX[row * 65 + c2i + 1];
            size_t gi = ((size_t)b * NN + m0 + row) * RR + c2i;
            *(float2*)(coefF + gi) = make_float2(v0, v1);
            store_pair2(oHi, oLo, gi, v0, v1);
        }
    } else {  // EPI == 5
        for (int i = tid; i < 4096; i += 256) {
            int row = i >> 5, c2i = (i & 31) * 2;
            size_t gi = ((size_t)b * NN + m0 + row) * RR + c2i;
            float2 cv = *(const float2*)(coefF + gi);
            float v0 = cv.x * sX[row * 65 + c2i] / (sD[row * 65 + c2i] + EPSV);
            float v1 = cv.y * sX[row * 65 + c2i + 1] / (sD[row * 65 + c2i + 1] + EPSV);
            *(float2*)(coefF + gi) = make_float2(v0, v1);
            store_pair2(oHi, oLo, gi, v0, v1);
            sX[row * 65 + c2i] = v0; sX[row * 65 + c2i + 1] = v1;
        }
        __syncthreads();
        for (int i = tid; i < 4096; i += 256) {
            int col = i >> 6, r2 = (i & 63) * 2;
            float v0 = sX[r2 * 65 + col], v1 = sX[(r2 + 1) * 65 + col];
            size_t gi = (size_t)b * RR * NN + (size_t)col * NN + m0 + r2;
            store_pair2(tHi, tLo, gi, v0, v1);
        }
    }
}

// -------- SIMT helpers --------
__global__ void k_norm_bases(const float* __restrict__ b0) {
    int b = blockIdx.x;
    __shared__ float part[8][64];
    __shared__ float inv[64];
    int r = threadIdx.x & 63, g = threadIdx.x >> 6;
    float s = 0.f;
    for (int d = g; d < CC; d += 8) { float v = b0[((size_t)b * CC + d) * RR + r]; s += v * v; }
    part[g][r] = s;
    __syncthreads();
    if (g == 0) {
        float t = 0.f;
        #pragma unroll
        for (int i = 0; i < 8; i++) t += part[i][r];
        inv[r] = 1.0f / fmaxf(sqrtf(t), 1e-12f);
    }
    __syncthreads();
    for (int d = g; d < CC; d += 8) {
        size_t i = ((size_t)b * CC + d) * RR + r;
        g_bases[i] = b0[i] * inv[r];
    }
}

__global__ void __launch_bounds__(256) k_ata(const float* __restrict__ Mb, size_t mS,
                                             int kPB, float* __restrict__ out, int nsp) {
    int sp = blockIdx.x, b = blockIdx.y;
    const float* M = Mb + (size_t)b * mS + (size_t)sp * kPB * RR;
    __shared__ float S[64][64];
    int t = threadIdx.x, rI = (t & 15) * 4, sI = (t >> 4) * 4;
    float acc[4][4] = {};
    for (int k0 = 0; k0 < kPB; k0 += 64) {
        #pragma unroll
        for (int p = 0; p < 4; p++) {
            int kr = (t >> 4) + p * 16;
            *(float4*)&S[kr][(t & 15) * 4] = *(const float4*)(M + (size_t)(k0 + kr) * RR + (t & 15) * 4);
        }
        __syncthreads();
        #pragma unroll
        for (int k = 0; k < 64; k++) {
            float4 av = *(const float4*)&S[k][rI];
            float4 bv = *(const float4*)&S[k][sI];
            float a[4] = {av.x, av.y, av.z, av.w}, bb[4] = {bv.x, bv.y, bv.z, bv.w};
            #pragma unroll
            for (int i = 0; i < 4; i++)
                #pragma unroll
                for (int j = 0; j < 4; j++) acc[i][j] = fmaf(a[i], bb[j], acc[i][j]);
        }
        __syncthreads();
    }
    float* o = out + ((size_t)b * nsp + sp) * (RR * RR);
    #pragma unroll
    for (int i = 0; i < 4; i++)
        *(float4*)&o[(size_t)(rI + i) * RR + sI] =
            make_float4(acc[i][0], acc[i][1], acc[i][2], acc[i][3]);
}

// bases update: reduce ctcp(16)+xcp(8), MU, write bases + coalesced bT pairs
__global__ void __launch_bounds__(256) k_bup() {
    int b = blockIdx.y, d0 = blockIdx.x * 64;
    __shared__ float ctc[64][65];
    __shared__ float bs[64][65];
    __shared__ float xcs[64][65];
    int t = threadIdx.x;
    for (int i = t; i < 4096; i += 256) {
        float v = 0.f;
        #pragma unroll 4
        for (int k = 0; k < 16; k++) v += g_ctcp[((size_t)(b * 16 + k)) * 4096 + i];
        ctc[i >> 6][i & 63] = v;
    }
    for (int i = t; i < 4096; i += 256) {
        int d = i >> 6, r = i & 63;
        bs[d][r] = g_bases[((size_t)b * CC + d0 + d) * RR + r];
        float v = 0.f;
        #pragma unroll
        for (int k = 0; k < 8; k++) v += g_xcp[((size_t)(b * 8 + k) * CC + d0 + d) * RR + r];
        xcs[d][r] = v;
    }
    __syncthreads();
    for (int i = t; i < 4096; i += 256) {
        int d = i >> 6, r = i & 63;
        float den = EPSV;
        #pragma unroll
        for (int s = 0; s < 64; s++) den = fmaf(bs[d][s], ctc[s][r], den);
        float v = bs[d][r] * xcs[d][r] / den;
        g_bases[((size_t)b * CC + d0 + d) * RR + r] = v;
        xcs[d][r] = v;   // stage updated bases
    }
    __syncthreads();
    for (int i = t; i < 2048; i += 256) {
        int r = i >> 5, d2 = (i & 31) * 2;
        size_t ti = ((size_t)b * RR + r) * CC + d0 + d2;
        store_pair2(g_bTh, g_bTl, ti, xcs[d2][r], xcs[d2 + 1][r]);
    }
}

__global__ void k_cvt(const float* __restrict__ s, bf16* __restrict__ hi, bf16* __restrict__ lo, int n) {
    int i = (blockIdx.x * 256 + threadIdx.x) * 2;
    if (i >= n) return;
    float2 v = *(const float2*)(s + i);
    store_pair2(hi, lo, i, v.x, v.y);
}

__global__ void k_tcvt(const float* __restrict__ src, bf16* __restrict__ dh, bf16* __restrict__ dl,
                       int rows, int cols) {
    __shared__ float t[32][33];
    int b = blockIdx.z;
    size_t sb = (size_t)b * rows * cols;
    int r0 = blockIdx.y * 32, c0 = blockIdx.x * 32;
    int tx = threadIdx.x & 31, ty = threadIdx.x >> 5;
    #pragma unroll
    for (int p = 0; p < 4; p++)
        t[ty + p * 8][tx] = src[sb + (size_t)(r0 + ty + p * 8) * cols + c0 + tx];
    __syncthreads();
    int tx2 = (threadIdx.x & 15) * 2, tyy = threadIdx.x >> 4;
    #pragma unroll
    for (int p = 0; p < 2; p++) {
        int cr = tyy + p * 16;
        size_t o = sb + (size_t)(c0 + cr) * rows + r0 + tx2;
        store_pair2(dh, dl, o, t[tx2][cr], t[tx2 + 1][cr]);
    }
}

__global__ void __launch_bounds__(256) k_wb(const float* __restrict__ Wc) {
    int b = blockIdx.y, m0 = blockIdx.x * 64;
    __shared__ float Ws[64][65];
    __shared__ float Bs[64][64];
    int t = threadIdx.x, mI = (t & 15) * 4, rI = (t >> 4) * 4;
    float acc[4][4] = {};
    for (int k0 = 0; k0 < CC; k0 += 64) {
        #pragma unroll
        for (int p = 0; p < 16; p++) {
            int lin = t + p * 256;
            Ws[lin >> 6][lin & 63] = Wc[(size_t)(m0 + (lin >> 6)) * CC + k0 + (lin & 63)];
            Bs[lin >> 6][lin & 63] = g_bases[((size_t)b * CC + k0 + (lin >> 6)) * RR + (lin & 63)];
        }
        __syncthreads();
        #pragma unroll
        for (int k = 0; k < 64; k++)
            #pragma unroll
            for (int i = 0; i < 4; i++)
                #pragma unroll
                for (int j = 0; j < 4; j++)
                    acc[i][j] = fmaf(Ws[mI + i][k], Bs[k][rI + j], acc[i][j]);
        __syncthreads();
    }
    #pragma unroll
    for (int i = 0; i < 4; i++)
        #pragma unroll
        for (int j = 0; j < 2; j++) {
            size_t idx = ((size_t)b * CC + m0 + mI + i) * RR + rI + j * 2;
            store_pair2(g_Wbh, g_Wbl, idx, acc[i][j * 2], acc[i][j * 2 + 1]);
        }
}

#define GSA(p, s) cudaGetSymbolAddress((void**)&p, s)

extern "C" void kernel_launch(void* const* d_in, const int* in_sizes, int n_in,
                              void* d_out, int out_size) {
    const float* x        = (const float*)d_in[0];
    const float* bases0   = (const float*)d_in[1];
    const float* w_lower  = (const float*)d_in[2];
    const float* b_lower  = (const float*)d_in[3];
    const float* w_cheese = (const float*)d_in[4];
    const float* b_cheese = (const float*)d_in[5];
    const float* w_upper  = (const float*)d_in[6];
    const float* c_short  = (const float*)d_in[7];
    const float* c_ham    = (const float*)d_in[8];
    float* out = (float*)d_out;

    float *bases, *coef, *btbp, *ctcp, *xcp;
    GSA(bases, g_bases); GSA(coef, g_coef); GSA(btbp, g_btbp); GSA(ctcp, g_ctcp); GSA(xcp, g_xcp);
    bf16 *WLh, *WLl, *WUh, *WUl, *Xth, *Xtl, *Hh, *Hl, *Hth, *Htl, *H2h, *H2l;
    bf16 *cTh, *cTl, *Ch, *Cl, *bTh, *bTl, *Wbh, *Wbl;
    GSA(WLh, g_WLh); GSA(WLl, g_WLl); GSA(WUh, g_WUh); GSA(WUl, g_WUl);
    GSA(Xth, g_Xth); GSA(Xtl, g_Xtl); GSA(Hh, g_Hh); GSA(Hl, g_Hl);
    GSA(Hth, g_Hth); GSA(Htl, g_Htl); GSA(H2h, g_H2h); GSA(H2l, g_H2l);
    GSA(cTh, g_cTh); GSA(cTl, g_cTl); GSA(Ch, g_Ch); GSA(Cl, g_Cl);
    GSA(bTh, g_bTh); GSA(bTl, g_bTl); GSA(Wbh, g_Wbh); GSA(Wbl, g_Wbl);

    const int SM128  = 3 * 2 * (128 + 128) * 40 * 2;  // 122880 (P=2)
    const int SM64P1 = 3 * 1 * (128 + 64) * 40 * 2;   // 46080  (P=1 pipeline)
    const int SM64E5 = 2 * 128 * 65 * 4;              // 66560  (EPI5 float staging sX+sD)
    cudaFuncSetAttribute((void*)k_mma<128, 1, 1, 3>, cudaFuncAttributeMaxDynamicSharedMemorySize, SM128);
    cudaFuncSetAttribute((void*)k_mma<128, 1, 2, 3>, cudaFuncAttributeMaxDynamicSharedMemorySize, SM128);
    cudaFuncSetAttribute((void*)k_mma<128, 1, 3, 3>, cudaFuncAttributeMaxDynamicSharedMemorySize, SM128);
    cudaFuncSetAttribute((void*)k_mma<64, 1, 4, 1>,  cudaFuncAttributeMaxDynamicSharedMemorySize, SM64P1);
    cudaFuncSetAttribute((void*)k_mma<64, 1, 5, 1>,  cudaFuncAttributeMaxDynamicSharedMemorySize, SM64E5);
    cudaFuncSetAttribute((void*)k_mma<64, 8, 0, 1>,  cudaFuncAttributeMaxDynamicSharedMemorySize, SM64P1);

    k_cvt<<<(CC * CC / 2 + 255) / 256, 256>>>(w_lower, WLh, WLl, CC * CC);
    k_cvt<<<(CC * CC / 2 + 255) / 256, 256>>>(w_upper, WUh, WUl, CC * CC);
    k_tcvt<<<dim3(NN / 32, CC / 32, BATCH), 256>>>(x, Xth, Xtl, CC, NN);
    k_norm_bases<<<BATCH, 512>>>(bases0);
    k_tcvt<<<dim3(RR / 32, CC / 32, BATCH), 256>>>(bases, bTh, bTl, CC, RR);

    // H = relu(WL @ X + b) -> H pairs + Ht pairs   (bf16x3)
    k_mma<128, 1, 1, 3><<<dim3(32, 4, BATCH), 256, SM128>>>(
        WLh, WLl, 0, CC, Xth, Xtl, (size_t)NN * CC, CC, CC,
        nullptr, 0, 0, Hh, Hl, b_lower, Hth, Htl,
        nullptr, nullptr, nullptr, nullptr, nullptr);

    // coef = softmax(Ht @ bT) -> coef fp32 + Ch/Cl pairs   (single bf16)
    k_mma<64, 1, 4, 1><<<dim3(1, 32, BATCH), 256, SM64P1>>>(
        Hth, Htl, (size_t)NN * CC, CC, bTh, bTl, (size_t)RR * CC, CC, CC,
        nullptr, 0, 0, Ch, Cl, nullptr, nullptr, nullptr,
        nullptr, nullptr, nullptr, coef, nullptr);

    for (int it = 0; it <= NSTEPS; it++) {
        // btb partials (8 k-splits of 64 rows)
        k_ata<<<dim3(8, BATCH), 256>>>(bases, (size_t)CC * RR, 64, btbp, 8);
        // coef MU: xtb GEMM + den GEMM + update -> coef + Ch/Cl + cT pairs   (single bf16)
        k_mma<64, 1, 5, 1><<<dim3(1, 32, BATCH), 256, SM64E5>>>(
            Hth, Htl, (size_t)NN * CC, CC, bTh, bTl, (size_t)RR * CC, CC, CC,
            nullptr, 0, 0, Ch, Cl, nullptr, cTh, cTl,
            nullptr, nullptr, nullptr, coef, btbp);
        if (it == NSTEPS) break;  // last = differentiable refinement, no bases update
        k_ata<<<dim3(16, BATCH), 256>>>(coef, (size_t)NN * RR, 256, ctcp, 16);
        // xc = H @ cT  (single bf16, split-K 8)
        k_mma<64, 8, 0, 1><<<dim3(8, 4, BATCH), 256, SM64P1>>>(
            Hh, Hl, (size_t)CC * NN, NN, cTh, cTl, (size_t)RR * NN, NN, NN / 8,
            xcp, (size_t)CC * RR, RR, nullptr, nullptr, nullptr, nullptr, nullptr,
            nullptr, nullptr, nullptr, nullptr, nullptr);
        k_bup<<<dim3(8, BATCH), 256>>>();   // bases MU + bT pairs
    }

    // fused cheese: H2[n][c2] = relu(coef @ (Wc@bases)^T + b_cheese)   (bf16x3)
    k_wb<<<dim3(CC / 64, BATCH), 256>>>(w_cheese);
    k_mma<128, 1, 2, 3><<<dim3(4, 32, BATCH), 256, SM128>>>(
        Ch, Cl, (size_t)NN * RR, RR, Wbh, Wbl, (size_t)CC * RR, RR, RR,
        nullptr, 0, 0, H2h, H2l, b_cheese, nullptr, nullptr,
        nullptr, nullptr, nullptr, nullptr, nullptr);
    // out = relu(c_ham * (WU @ H2) + c_short * x)   (bf16x3)
    k_mma<128, 1, 3, 3><<<dim3(32, 4, BATCH), 256, SM128>>>(
        WUh, WUl, 0, CC, H2h, H2l, (size_t)NN * CC, CC, CC,
        out, (size_t)CC * NN, NN, nullptr, nullptr, nullptr, nullptr, nullptr,
        x, c_ham, c_short, nullptr, nullptr);
    (void)in_sizes; (void)n_in; (void)out_size;
}

// round 14
// speedup vs baseline: 1.5031x; 1.0570x over previous
#include <cuda_runtime.h>
#include <cuda_bf16.h>
#include <cstdint>
#include <math.h>

#define BATCH 8
#define CC 512
#define NN 4096
#define RR 64
#define EPSV 1e-6f
#define NSTEPS 6
typedef __nv_bfloat16 bf16;
#define F2B(v) __float2bfloat16(v)
#define B2F(v) __bfloat162float(v)

__device__ __forceinline__ uint32_t smem_u32(const void* p) {
    uint32_t a;
    asm("{ .reg .u64 t; cvta.to.shared.u64 t, %1; cvt.u32.u64 %0, t; }" : "=r"(a) : "l"(p));
    return a;
}
__device__ __forceinline__ void cpa16(uint32_t s, const void* g) {
    asm volatile("cp.async.cg.shared.global [%0], [%1], 16;" :: "r"(s), "l"(g));
}
__device__ __forceinline__ void cpa16ca(uint32_t s, const void* g) {
    asm volatile("cp.async.ca.shared.global [%0], [%1], 16;" :: "r"(s), "l"(g));
}
#define CP_COMMIT() asm volatile("cp.async.commit_group;" ::: "memory")
#define CP_WAIT1()  asm volatile("cp.async.wait_group 1;" ::: "memory")
#define CP_WAIT0()  asm volatile("cp.async.wait_group 0;" ::: "memory")
__device__ __forceinline__ void ldsm4(uint32_t* d, uint32_t addr) {
    asm volatile("ldmatrix.sync.aligned.m8n8.x4.shared.b16 {%0,%1,%2,%3}, [%4];"
        : "=r"(d[0]), "=r"(d[1]), "=r"(d[2]), "=r"(d[3]) : "r"(addr));
}
__device__ __forceinline__ void mma16816(float* c, const uint32_t* a, const uint32_t* b) {
    asm volatile("mma.sync.aligned.m16n8k16.row.col.f32.bf16.bf16.f32 "
        "{%0,%1,%2,%3}, {%4,%5,%6,%7}, {%8,%9}, {%0,%1,%2,%3};"
        : "+f"(c[0]), "+f"(c[1]), "+f"(c[2]), "+f"(c[3])
        : "r"(a[0]), "r"(a[1]), "r"(a[2]), "r"(a[3]), "r"(b[0]), "r"(b[1]));
}
__device__ __forceinline__ void store_pair2(bf16* hi, bf16* lo, size_t idx, float v0, float v1) {
    bf16 h0 = F2B(v0), h1 = F2B(v1);
    *(__nv_bfloat162*)(hi + idx) = __halves2bfloat162(h0, h1);
    *(__nv_bfloat162*)(lo + idx) =
        __halves2bfloat162(F2B(v0 - B2F(h0)), F2B(v1 - B2F(h1)));
}

// -------- scratch --------
__device__ float g_bases[BATCH * CC * RR];
__device__ float g_coef[BATCH * NN * RR];
__device__ float g_btbp[BATCH * 8 * RR * RR];
__device__ float g_ctcp[BATCH * 16 * RR * RR];
__device__ float g_xcp[BATCH * 8 * CC * RR];
__device__ bf16 g_WLh[CC * CC], g_WLl[CC * CC], g_WUh[CC * CC], g_WUl[CC * CC];
__device__ bf16 g_Xth[BATCH * NN * CC], g_Xtl[BATCH * NN * CC];
__device__ bf16 g_Hh[BATCH * CC * NN], g_Hl[BATCH * CC * NN];
__device__ bf16 g_Hth[BATCH * NN * CC], g_Htl[BATCH * NN * CC];
__device__ bf16 g_H2h[BATCH * NN * CC], g_H2l[BATCH * NN * CC];
__device__ bf16 g_cTh[BATCH * RR * NN], g_cTl[BATCH * RR * NN];
__device__ bf16 g_Ch[BATCH * NN * RR], g_Cl[BATCH * NN * RR];
__device__ bf16 g_bTh[BATCH * RR * CC], g_bTl[BATCH * RR * CC];
__device__ bf16 g_Wbh[BATCH * CC * RR], g_Wbl[BATCH * CC * RR];

// ============ cp.async mma.sync GEMM ============
// NPROD=3: bf16x3 2-plane; NPROD=1: 1-plane. NSTG: pipeline stages (2 or 3).
// D[m][n'] = sum_k A[m][k]*B[n'][k]. 8 warps 4(M)x2(N), tile 128xTN, K-chunk 32.
// EPI 0: fp32 (split-K). 1: lower. 2: cheese. 3: upper. 4: softmax init. 5: coef MU.
template <int TN, int SPLITK, int EPI, int NPROD, int NSTG>
__global__ void __launch_bounds__(256) k_mma(
    const bf16* __restrict__ Ahi, const bf16* __restrict__ Alo, size_t aB, int aS,
    const bf16* __restrict__ Bhi, const bf16* __restrict__ Blo, size_t bB, int bS,
    int kLen,
    float* __restrict__ outF, size_t oB, int oS,
    bf16* __restrict__ oHi, bf16* __restrict__ oLo, const float* __restrict__ bias,
    bf16* __restrict__ tHi, bf16* __restrict__ tLo,
    const float* __restrict__ Xres, const float* __restrict__ sH, const float* __restrict__ sS,
    float* __restrict__ coefF, const float* __restrict__ btbP)
{
    extern __shared__ char smem[];
    constexpr int NF = TN / 16;
    constexpr int WN = TN / 2;
    constexpr int SW = TN + 1;
    constexpr int HTN = TN / 2;
    constexpr int CSH2 = (TN == 128) ? 6 : 5;
    constexpr int P = (NPROD == 3) ? 2 : 1;        // bf16 planes resident in smem
    constexpr int SS = P * (128 + TN) * 40;        // bf16 elems per stage
    bf16* sb16 = (bf16*)smem;
    float* stage = (float*)smem;
    uint32_t smb = smem_u32(smem);

    int tid = threadIdx.x, lane = tid & 31, wid = tid >> 5;
    int wm = wid >> 1, wn = wid & 1;
    int b = blockIdx.z;
    int ks = (SPLITK > 1) ? blockIdx.x : 0;
    int n0 = (SPLITK > 1) ? 0 : blockIdx.x * TN;
    int m0 = blockIdx.y * 128;

    const bf16* A0 = Ahi + (size_t)b * aB + (size_t)m0 * aS + ks * kLen;
    const bf16* A1 = (NPROD == 3) ? Alo + (size_t)b * aB + (size_t)m0 * aS + ks * kLen : nullptr;
    const bf16* B0 = Bhi + (size_t)b * bB + (size_t)n0 * bS + ks * kLen;
    const bf16* B1 = (NPROD == 3) ? Blo + (size_t)b * bB + (size_t)n0 * bS + ks * kLen : nullptr;

    float c[2][NF][4];
    #pragma unroll
    for (int i = 0; i < 2; i++)
        #pragma unroll
        for (int j = 0; j < NF; j++)
            #pragma unroll
            for (int q = 0; q < 4; q++) c[i][j][q] = 0.f;

    auto aoff = [&](int st, int pl, int r, int col) { return st * SS + pl * (128 * 40) + r * 40 + col; };
    auto boff = [&](int st, int pl, int r, int col) { return st * SS + P * (128 * 40) + pl * (TN * 40) + r * 40 + col; };

    auto loadst = [&](int st, int koff) {
        #pragma unroll
        for (int i = tid; i < 512; i += 256) {
            int r = i >> 2, q = i & 3;
            size_t o = (size_t)r * aS + koff + q * 8;
            cpa16ca(smb + 2u * aoff(st, 0, r, q * 8), A0 + o);
            if (NPROD == 3) cpa16ca(smb + 2u * aoff(st, 1, r, q * 8), A1 + o);
        }
        #pragma unroll
        for (int i = tid; i < TN * 4; i += 256) {
            int r = i >> 2, q = i & 3;
            size_t o = (size_t)r * bS + koff + q * 8;
            cpa16(smb + 2u * boff(st, 0, r, q * 8), B0 + o);
            if (NPROD == 3) cpa16(smb + 2u * boff(st, 1, r, q * 8), B1 + o);
        }
    };
    auto compute = [&](int st, float (*acc)[NF][4]) {
        #pragma unroll
        for (int kk = 0; kk < 32; kk += 16) {
            uint32_t a[2][2][4];
            #pragma unroll
            for (int pl = 0; pl < P; pl++)
                #pragma unroll
                for (int mf = 0; mf < 2; mf++)
                    ldsm4(a[pl][mf], smb + 2u * aoff(st, pl, wm * 32 + mf * 16 + (lane & 15),
                                                     kk + (lane >> 4) * 8));
            #pragma unroll
            for (int nf2 = 0; nf2 < NF / 2; nf2++) {
                uint32_t bq0[4];
                ldsm4(bq0, smb + 2u * boff(st, 0, wn * WN + nf2 * 16 + (lane & 15),
                                           kk + (lane >> 4) * 8));
                uint32_t bh[2][2] = {{bq0[0], bq0[2]}, {bq0[1], bq0[3]}};
                if (NPROD == 3) {
                    uint32_t bq1[4];
                    ldsm4(bq1, smb + 2u * boff(st, 1, wn * WN + nf2 * 16 + (lane & 15),
                                               kk + (lane >> 4) * 8));
                    uint32_t bl[2][2] = {{bq1[0], bq1[2]}, {bq1[1], bq1[3]}};
                    #pragma unroll
                    for (int hf = 0; hf < 2; hf++)
                        #pragma unroll
                        for (int mf = 0; mf < 2; mf++) {
                            mma16816(acc[mf][2 * nf2 + hf], a[0][mf], bh[hf]);
                            mma16816(acc[mf][2 * nf2 + hf], a[0][mf], bl[hf]);
                            mma16816(acc[mf][2 * nf2 + hf], a[1][mf], bh[hf]);
                        }
                } else {
                    #pragma unroll
                    for (int hf = 0; hf < 2; hf++)
                        #pragma unroll
                        for (int mf = 0; mf < 2; mf++)
                            mma16816(acc[mf][2 * nf2 + hf], a[0][mf], bh[hf]);
                }
            }
        }
    };

    int nch = kLen / 32;
    if (NSTG == 3) {
        #pragma unroll
        for (int s = 0; s < 2; s++) {
            if (s < nch) loadst(s, s * 32);
            CP_COMMIT();
        }
        for (int ch = 0; ch < nch; ch++) {
            CP_WAIT1();
            __syncthreads();
            if (ch + 2 < nch) loadst((ch + 2) % 3, (ch + 2) * 32);
            CP_COMMIT();
            compute(ch % 3, c);
        }
    } else {  // NSTG == 2: single chunk in flight, load(ch+1) overlaps compute(ch)
        loadst(0, 0);
        CP_COMMIT();
        for (int ch = 0; ch < nch; ch++) {
            CP_WAIT0();
            __syncthreads();
            if (ch + 1 < nch) { loadst((ch + 1) & 1, (ch + 1) * 32); CP_COMMIT(); }
            compute(ch & 1, c);
        }
    }
    __syncthreads();

    // ---- EPI5: den = coef @ btb on tensor cores (stages 0,1) ----
    float c2[2][NF][4];
    if (EPI == 5) {
        #pragma unroll
        for (int i = 0; i < 2; i++)
            #pragma unroll
            for (int j = 0; j < NF; j++)
                #pragma unroll
                for (int q = 0; q < 4; q++) c2[i][j][q] = 0.f;
        for (int i = tid; i < 1024; i += 256) {
            int r = i >> 3, q = i & 7, st = q >> 2, qq = q & 3;
            size_t gi = ((size_t)b * NN + m0 + r) * RR + st * 32 + qq * 8;
            *(uint4*)&sb16[aoff(st, 0, r, qq * 8)] = *(const uint4*)(oHi + gi);
            if (NPROD == 3)
                *(uint4*)&sb16[aoff(st, 1, r, qq * 8)] = *(const uint4*)(oLo + gi);
        }
        // btb: reduce 8 k-partials, convert to bf16 in smem B region
        for (int i = tid; i < 4096; i += 256) {
            int r = i >> 6, ck = i & 63;
            float v = 0.f;
            #pragma unroll
            for (int k = 0; k < 8; k++) v += btbP[((size_t)(b * 8 + k)) * 4096 + i];
            int st = ck >> 5, cc = ck & 31;
            bf16 h = F2B(v);
            sb16[boff(st, 0, r, cc)] = h;
            if (NPROD == 3) sb16[boff(st, 1, r, cc)] = F2B(v - B2F(h));
        }
        __syncthreads();
        compute(0, c2);
        compute(1, c2);
        __syncthreads();
    }

    // ---- stage accumulators ----
    float* sX = stage;
    float* sD = stage + 128 * 65;
    #pragma unroll
    for (int mf = 0; mf < 2; mf++)
        #pragma unroll
        for (int nf = 0; nf < NF; nf++) {
            int row = wm * 32 + mf * 16 + (lane >> 2);
            int col = wn * WN + nf * 8 + (lane & 3) * 2;
            if (EPI >= 4) {
                sX[row * 65 + col] = c[mf][nf][0];       sX[row * 65 + col + 1] = c[mf][nf][1];
                sX[(row + 8) * 65 + col] = c[mf][nf][2]; sX[(row + 8) * 65 + col + 1] = c[mf][nf][3];
                if (EPI == 5) {
                    sD[row * 65 + col] = c2[mf][nf][0];       sD[row * 65 + col + 1] = c2[mf][nf][1];
                    sD[(row + 8) * 65 + col] = c2[mf][nf][2]; sD[(row + 8) * 65 + col + 1] = c2[mf][nf][3];
                }
            } else {
                stage[row * SW + col] = c[mf][nf][0];       stage[row * SW + col + 1] = c[mf][nf][1];
                stage[(row + 8) * SW + col] = c[mf][nf][2]; stage[(row + 8) * SW + col + 1] = c[mf][nf][3];
            }
        }
    __syncthreads();

    if (EPI == 0) {
        for (int i = tid; i < 128 * HTN; i += 256) {
            int row = i >> CSH2, c2i = (i & (HTN - 1)) * 2;
            size_t idx = (size_t)(b * SPLITK + ks) * oB + (size_t)(m0 + row) * oS + n0 + c2i;
            *(float2*)(outF + idx) = make_float2(stage[row * SW + c2i], stage[row * SW + c2i + 1]);
        }
    } else if (EPI == 1) {
        for (int i = tid; i < 128 * HTN; i += 256) {
            int row = i >> CSH2, c2i = (i & (HTN - 1)) * 2;
            float bv = bias[m0 + row];
            float v0 = fmaxf(stage[row * SW + c2i] + bv, 0.f);
            float v1 = fmaxf(stage[row * SW + c2i + 1] + bv, 0.f);
            size_t idx = (size_t)b * (CC * NN) + (size_t)(m0 + row) * NN + n0 + c2i;
            store_pair2(oHi, oLo, idx, v0, v1);
            stage[row * SW + c2i] = v0; stage[row * SW + c2i + 1] = v1;
        }
        __syncthreads();
        for (int i = tid; i < 64 * TN; i += 256) {
            int col = i >> 6, r2 = (i & 63) * 2;
            float v0 = stage[r2 * SW + col], v1 = stage[(r2 + 1) * SW + col];
            size_t idx = (size_t)b * (NN * CC) + (size_t)(n0 + col) * CC + m0 + r2;
            store_pair2(tHi, tLo, idx, v0, v1);
        }
    } else if (EPI == 2) {
        for (int i = tid; i < 128 * HTN; i += 256) {
            int row = i >> CSH2, c2i = (i & (HTN - 1)) * 2;
            float v0 = fmaxf(stage[row * SW + c2i] + bias[n0 + c2i], 0.f);
            float v1 = fmaxf(stage[row * SW + c2i + 1] + bias[n0 + c2i + 1], 0.f);
            size_t idx = (size_t)b * (NN * CC) + (size_t)(m0 + row) * CC + n0 + c2i;
            store_pair2(oHi, oLo, idx, v0, v1);
        }
    } else if (EPI == 3) {
        float a = sH[0], s = sS[0];
        for (int i = tid; i < 128 * HTN; i += 256) {
            int row = i >> CSH2, c2i = (i & (HTN - 1)) * 2;
            size_t idx = (size_t)b * oB + (size_t)(m0 + row) * oS + n0 + c2i;
            float2 xv = *(const float2*)(Xres + idx);
            *(float2*)(outF + idx) = make_float2(
                fmaxf(a * stage[row * SW + c2i] + s * xv.x, 0.f),
                fmaxf(a * stage[row * SW + c2i + 1] + s * xv.y, 0.f));
        }
    } else if (EPI == 4) {
        if (tid < 128) {
            float mx = -1e30f;
            for (int cc2 = 0; cc2 < 64; cc2++) mx = fmaxf(mx, sX[tid * 65 + cc2]);
            float s = 0.f;
            for (int cc2 = 0; cc2 < 64; cc2++) {
                float e = expf(sX[tid * 65 + cc2] - mx);
                sX[tid * 65 + cc2] = e; s += e;
            }
            float inv = 1.0f / s;
            for (int cc2 = 0; cc2 < 64; cc2++) sX[tid * 65 + cc2] *= inv;
        }
        __syncthreads();
        for (int i = tid; i < 4096; i += 256) {
            int row = i >> 5, c2i = (i & 31) * 2;
            float v0 = sX[row * 65 + c2i], v1 = sX[row * 65 + c2i + 1];
            size_t gi = ((size_t)b * NN + m0 + row) * RR + c2i;
            *(float2*)(coefF + gi) = make_float2(v0, v1);
            store_pair2(oHi, oLo, gi, v0, v1);
        }
    } else {  // EPI == 5
        for (int i = tid; i < 4096; i += 256) {
            int row = i >> 5, c2i = (i & 31) * 2;
            size_t gi = ((size_t)b * NN + m0 + row) * RR + c2i;
            float2 cv = *(const float2*)(coefF + gi);
            float v0 = cv.x * sX[row * 65 + c2i] / (sD[row * 65 + c2i] + EPSV);
            float v1 = cv.y * sX[row * 65 + c2i + 1] / (sD[row * 65 + c2i + 1] + EPSV);
            *(float2*)(coefF + gi) = make_float2(v0, v1);
            store_pair2(oHi, oLo, gi, v0, v1);
            sX[row * 65 + c2i] = v0; sX[row * 65 + c2i + 1] = v1;
        }
        __syncthreads();
        for (int i = tid; i < 4096; i += 256) {
            int col = i >> 6, r2 = (i & 63) * 2;
            float v0 = sX[r2 * 65 + col], v1 = sX[(r2 + 1) * 65 + col];
            size_t gi = (size_t)b * RR * NN + (size_t)col * NN + m0 + r2;
            store_pair2(tHi, tLo, gi, v0, v1);
        }
    }
}

// -------- SIMT helpers --------
__global__ void k_norm_bases(const float* __restrict__ b0) {
    int b = blockIdx.x;
    __shared__ float part[8][64];
    __shared__ float inv[64];
    int r = threadIdx.x & 63, g = threadIdx.x >> 6;
    float s = 0.f;
    for (int d = g; d < CC; d += 8) { float v = b0[((size_t)b * CC + d) * RR + r]; s += v * v; }
    part[g][r] = s;
    __syncthreads();
    if (g == 0) {
        float t = 0.f;
        #pragma unroll
        for (int i = 0; i < 8; i++) t += part[i][r];
        inv[r] = 1.0f / fmaxf(sqrtf(t), 1e-12f);
    }
    __syncthreads();
    for (int d = g; d < CC; d += 8) {
        size_t i = ((size_t)b * CC + d) * RR + r;
        g_bases[i] = b0[i] * inv[r];
    }
}

__global__ void __launch_bounds__(256) k_ata(const float* __restrict__ Mb, size_t mS,
                                             int kPB, float* __restrict__ out, int nsp) {
    int sp = blockIdx.x, b = blockIdx.y;
    const float* M = Mb + (size_t)b * mS + (size_t)sp * kPB * RR;
    __shared__ float S[64][64];
    int t = threadIdx.x, rI = (t & 15) * 4, sI = (t >> 4) * 4;
    float acc[4][4] = {};
    for (int k0 = 0; k0 < kPB; k0 += 64) {
        #pragma unroll
        for (int p = 0; p < 4; p++) {
            int kr = (t >> 4) + p * 16;
            *(float4*)&S[kr][(t & 15) * 4] = *(const float4*)(M + (size_t)(k0 + kr) * RR + (t & 15) * 4);
        }
        __syncthreads();
        #pragma unroll
        for (int k = 0; k < 64; k++) {
            float4 av = *(const float4*)&S[k][rI];
            float4 bv = *(const float4*)&S[k][sI];
            float a[4] = {av.x, av.y, av.z, av.w}, bb[4] = {bv.x, bv.y, bv.z, bv.w};
            #pragma unroll
            for (int i = 0; i < 4; i++)
                #pragma unroll
                for (int j = 0; j < 4; j++) acc[i][j] = fmaf(a[i], bb[j], acc[i][j]);
        }
        __syncthreads();
    }
    float* o = out + ((size_t)b * nsp + sp) * (RR * RR);
    #pragma unroll
    for (int i = 0; i < 4; i++)
        *(float4*)&o[(size_t)(rI + i) * RR + sI] =
            make_float4(acc[i][0], acc[i][1], acc[i][2], acc[i][3]);
}

// bases update: reduce ctcp(16)+xcp(8), MU, write bases + coalesced bT pairs
__global__ void __launch_bounds__(256) k_bup() {
    int b = blockIdx.y, d0 = blockIdx.x * 64;
    __shared__ float ctc[64][65];
    __shared__ float bs[64][65];
    __shared__ float xcs[64][65];
    int t = threadIdx.x;
    for (int i = t; i < 4096; i += 256) {
        float v = 0.f;
        #pragma unroll 4
        for (int k = 0; k < 16; k++) v += g_ctcp[((size_t)(b * 16 + k)) * 4096 + i];
        ctc[i >> 6][i & 63] = v;
    }
    for (int i = t; i < 4096; i += 256) {
        int d = i >> 6, r = i & 63;
        bs[d][r] = g_bases[((size_t)b * CC + d0 + d) * RR + r];
        float v = 0.f;
        #pragma unroll
        for (int k = 0; k < 8; k++) v += g_xcp[((size_t)(b * 8 + k) * CC + d0 + d) * RR + r];
        xcs[d][r] = v;
    }
    __syncthreads();
    for (int i = t; i < 4096; i += 256) {
        int d = i >> 6, r = i & 63;
        float den = EPSV;
        #pragma unroll
        for (int s = 0; s < 64; s++) den = fmaf(bs[d][s], ctc[s][r], den);
        float v = bs[d][r] * xcs[d][r] / den;
        g_bases[((size_t)b * CC + d0 + d) * RR + r] = v;
        xcs[d][r] = v;   // stage updated bases
    }
    __syncthreads();
    for (int i = t; i < 2048; i += 256) {
        int r = i >> 5, d2 = (i & 31) * 2;
        size_t ti = ((size_t)b * RR + r) * CC + d0 + d2;
        store_pair2(g_bTh, g_bTl, ti, xcs[d2][r], xcs[d2 + 1][r]);
    }
}

__global__ void k_cvt(const float* __restrict__ s, bf16* __restrict__ hi, bf16* __restrict__ lo, int n) {
    int i = (blockIdx.x * 256 + threadIdx.x) * 2;
    if (i >= n) return;
    float2 v = *(const float2*)(s + i);
    store_pair2(hi, lo, i, v.x, v.y);
}

__global__ void k_tcvt(const float* __restrict__ src, bf16* __restrict__ dh, bf16* __restrict__ dl,
                       int rows, int cols) {
    __shared__ float t[32][33];
    int b = blockIdx.z;
    size_t sb = (size_t)b * rows * cols;
    int r0 = blockIdx.y * 32, c0 = blockIdx.x * 32;
    int tx = threadIdx.x & 31, ty = threadIdx.x >> 5;
    #pragma unroll
    for (int p = 0; p < 4; p++)
        t[ty + p * 8][tx] = src[sb + (size_t)(r0 + ty + p * 8) * cols + c0 + tx];
    __syncthreads();
    int tx2 = (threadIdx.x & 15) * 2, tyy = threadIdx.x >> 4;
    #pragma unroll
    for (int p = 0; p < 2; p++) {
        int cr = tyy + p * 16;
        size_t o = sb + (size_t)(c0 + cr) * rows + r0 + tx2;
        store_pair2(dh, dl, o, t[tx2][cr], t[tx2 + 1][cr]);
    }
}

__global__ void __launch_bounds__(256) k_wb(const float* __restrict__ Wc) {
    int b = blockIdx.y, m0 = blockIdx.x * 64;
    __shared__ float Ws[64][65];
    __shared__ float Bs[64][64];
    int t = threadIdx.x, mI = (t & 15) * 4, rI = (t >> 4) * 4;
    float acc[4][4] = {};
    for (int k0 = 0; k0 < CC; k0 += 64) {
        #pragma unroll
        for (int p = 0; p < 16; p++) {
            int lin = t + p * 256;
            Ws[lin >> 6][lin & 63] = Wc[(size_t)(m0 + (lin >> 6)) * CC + k0 + (lin & 63)];
            Bs[lin >> 6][lin & 63] = g_bases[((size_t)b * CC + k0 + (lin >> 6)) * RR + (lin & 63)];
        }
        __syncthreads();
        #pragma unroll
        for (int k = 0; k < 64; k++)
            #pragma unroll
            for (int i = 0; i < 4; i++)
                #pragma unroll
                for (int j = 0; j < 4; j++)
                    acc[i][j] = fmaf(Ws[mI + i][k], Bs[k][rI + j], acc[i][j]);
        __syncthreads();
    }
    #pragma unroll
    for (int i = 0; i < 4; i++)
        #pragma unroll
        for (int j = 0; j < 2; j++) {
            size_t idx = ((size_t)b * CC + m0 + mI + i) * RR + rI + j * 2;
            store_pair2(g_Wbh, g_Wbl, idx, acc[i][j * 2], acc[i][j * 2 + 1]);
        }
}

#define GSA(p, s) cudaGetSymbolAddress((void**)&p, s)

extern "C" void kernel_launch(void* const* d_in, const int* in_sizes, int n_in,
                              void* d_out, int out_size) {
    const float* x        = (const float*)d_in[0];
    const float* bases0   = (const float*)d_in[1];
    const float* w_lower  = (const float*)d_in[2];
    const float* b_lower  = (const float*)d_in[3];
    const float* w_cheese = (const float*)d_in[4];
    const float* b_cheese = (const float*)d_in[5];
    const float* w_upper  = (const float*)d_in[6];
    const float* c_short  = (const float*)d_in[7];
    const float* c_ham    = (const float*)d_in[8];
    float* out = (float*)d_out;

    float *bases, *coef, *btbp, *ctcp, *xcp;
    GSA(bases, g_bases); GSA(coef, g_coef); GSA(btbp, g_btbp); GSA(ctcp, g_ctcp); GSA(xcp, g_xcp);
    bf16 *WLh, *WLl, *WUh, *WUl, *Xth, *Xtl, *Hh, *Hl, *Hth, *Htl, *H2h, *H2l;
    bf16 *cTh, *cTl, *Ch, *Cl, *bTh, *bTl, *Wbh, *Wbl;
    GSA(WLh, g_WLh); GSA(WLl, g_WLl); GSA(WUh, g_WUh); GSA(WUl, g_WUl);
    GSA(Xth, g_Xth); GSA(Xtl, g_Xtl); GSA(Hh, g_Hh); GSA(Hl, g_Hl);
    GSA(Hth, g_Hth); GSA(Htl, g_Htl); GSA(H2h, g_H2h); GSA(H2l, g_H2l);
    GSA(cTh, g_cTh); GSA(cTl, g_cTl); GSA(Ch, g_Ch); GSA(Cl, g_Cl);
    GSA(bTh, g_bTh); GSA(bTl, g_bTl); GSA(Wbh, g_Wbh); GSA(Wbl, g_Wbl);

    const int SM128  = 2 * 2 * (128 + 128) * 40 * 2;  // 81920 (P=2, 2-stage -> 2 blocks/SM)
    const int SM64P1 = 3 * 1 * (128 + 64) * 40 * 2;   // 46080 (P=1, 3-stage)
    const int SM64E5 = 2 * 128 * 65 * 4;              // 66560 (EPI5 float staging sX+sD)
    cudaFuncSetAttribute((void*)k_mma<128, 1, 1, 3, 2>, cudaFuncAttributeMaxDynamicSharedMemorySize, SM128);
    cudaFuncSetAttribute((void*)k_mma<128, 1, 2, 3, 2>, cudaFuncAttributeMaxDynamicSharedMemorySize, SM128);
    cudaFuncSetAttribute((void*)k_mma<128, 1, 3, 3, 2>, cudaFuncAttributeMaxDynamicSharedMemorySize, SM128);
    cudaFuncSetAttribute((void*)k_mma<64, 1, 4, 1, 3>,  cudaFuncAttributeMaxDynamicSharedMemorySize, SM64P1);
    cudaFuncSetAttribute((void*)k_mma<64, 1, 5, 1, 3>,  cudaFuncAttributeMaxDynamicSharedMemorySize, SM64E5);
    cudaFuncSetAttribute((void*)k_mma<64, 8, 0, 1, 3>,  cudaFuncAttributeMaxDynamicSharedMemorySize, SM64P1);

    k_cvt<<<(CC * CC / 2 + 255) / 256, 256>>>(w_lower, WLh, WLl, CC * CC);
    k_cvt<<<(CC * CC / 2 + 255) / 256, 256>>>(w_upper, WUh, WUl, CC * CC);
    k_tcvt<<<dim3(NN / 32, CC / 32, BATCH), 256>>>(x, Xth, Xtl, CC, NN);
    k_norm_bases<<<BATCH, 512>>>(bases0);
    k_tcvt<<<dim3(RR / 32, CC / 32, BATCH), 256>>>(bases, bTh, bTl, CC, RR);

    // H = relu(WL @ X + b) -> H pairs + Ht pairs   (bf16x3, 2-stage)
    k_mma<128, 1, 1, 3, 2><<<dim3(32, 4, BATCH), 256, SM128>>>(
        WLh, WLl, 0, CC, Xth, Xtl, (size_t)NN * CC, CC, CC,
        nullptr, 0, 0, Hh, Hl, b_lower, Hth, Htl,
        nullptr, nullptr, nullptr, nullptr, nullptr);

    // coef = softmax(Ht @ bT) -> coef fp32 + Ch/Cl pairs   (single bf16)
    k_mma<64, 1, 4, 1, 3><<<dim3(1, 32, BATCH), 256, SM64P1>>>(
        Hth, Htl, (size_t)NN * CC, CC, bTh, bTl, (size_t)RR * CC, CC, CC,
        nullptr, 0, 0, Ch, Cl, nullptr, nullptr, nullptr,
        nullptr, nullptr, nullptr, coef, nullptr);

    for (int it = 0; it <= NSTEPS; it++) {
        // btb partials (8 k-splits of 64 rows)
        k_ata<<<dim3(8, BATCH), 256>>>(bases, (size_t)CC * RR, 64, btbp, 8);
        // coef MU: xtb GEMM + den GEMM + update -> coef + Ch/Cl + cT pairs   (single bf16)
        k_mma<64, 1, 5, 1, 3><<<dim3(1, 32, BATCH), 256, SM64E5>>>(
            Hth, Htl, (size_t)NN * CC, CC, bTh, bTl, (size_t)RR * CC, CC, CC,
            nullptr, 0, 0, Ch, Cl, nullptr, cTh, cTl,
            nullptr, nullptr, nullptr, coef, btbp);
        if (it == NSTEPS) break;  // last = differentiable refinement, no bases update
        k_ata<<<dim3(16, BATCH), 256>>>(coef, (size_t)NN * RR, 256, ctcp, 16);
        // xc = H @ cT  (single bf16, split-K 8)
        k_mma<64, 8, 0, 1, 3><<<dim3(8, 4, BATCH), 256, SM64P1>>>(
            Hh, Hl, (size_t)CC * NN, NN, cTh, cTl, (size_t)RR * NN, NN, NN / 8,
            xcp, (size_t)CC * RR, RR, nullptr, nullptr, nullptr, nullptr, nullptr,
            nullptr, nullptr, nullptr, nullptr, nullptr);
        k_bup<<<dim3(8, BATCH), 256>>>();   // bases MU + bT pairs
    }

    // fused cheese: H2[n][c2] = relu(coef @ (Wc@bases)^T + b_cheese)   (bf16x3, 2-stage)
    k_wb<<<dim3(CC / 64, BATCH), 256>>>(w_cheese);
    k_mma<128, 1, 2, 3, 2><<<dim3(4, 32, BATCH), 256, SM128>>>(
        Ch, Cl, (size_t)NN * RR, RR, Wbh, Wbl, (size_t)CC * RR, RR, RR,
        nullptr, 0, 0, H2h, H2l, b_cheese, nullptr, nullptr,
        nullptr, nullptr, nullptr, nullptr, nullptr);
    // out = relu(c_ham * (WU @ H2) + c_short * x)   (bf16x3, 2-stage)
    k_mma<128, 1, 3, 3, 2><<<dim3(32, 4, BATCH), 256, SM128>>>(
        WUh, WUl, 0, CC, H2h, H2l, (size_t)NN * CC, CC, CC,
        out, (size_t)CC * NN, NN, nullptr, nullptr, nullptr, nullptr, nullptr,
        x, c_ham, c_short, nullptr, nullptr);
    (void)in_sizes; (void)n_in; (void)out_size;
}